// round 11
// baseline (speedup 1.0000x reference)
#include <cuda_runtime.h>
#include <cuda_bf16.h>
#include <cuda_fp16.h>
#include <cstdint>

#define N_NODES 50000
#define MAX_E   800000

// ---------------- device scratch ------------------------------------------
__device__ float g_Q[N_NODES * 128];
__device__ __half g_KVh[N_NODES * 256];            // [node][K:128 | V:128] fp16
__device__ float g_P[256];                         // softmax(S): [4][64]
// W packed in mma b-frag order: [ph][kt:8][nt:16][lane:32][8 bf16: hi w0b0,w0b1,w1b0,w1b1, lo ...]
__device__ __nv_bfloat16 g_Wf[3 * 8 * 16 * 32 * 8];
// CSR scratch
__device__ int g_cnt[N_NODES + 1];
__device__ int g_off[N_NODES + 1];
__device__ int g_pos[N_NODES + 1];
__device__ int g_esrc[MAX_E];

// ---------------- helpers --------------------------------------------------
__device__ __forceinline__ uint32_t smem_u32(const void* p) {
    uint32_t a;
    asm("{ .reg .u64 t; cvta.to.shared.u64 t, %1; cvt.u32.u64 %0, t; }" : "=r"(a) : "l"(p));
    return a;
}
__device__ __forceinline__ void ldm_x4(uint32_t* r, uint32_t addr) {
    asm volatile("ldmatrix.sync.aligned.m8n8.x4.shared.b16 {%0,%1,%2,%3}, [%4];"
                 : "=r"(r[0]), "=r"(r[1]), "=r"(r[2]), "=r"(r[3]) : "r"(addr));
}
__device__ __forceinline__ void mma16816(float* d, const uint32_t* a, uint32_t b0, uint32_t b1) {
    asm volatile("mma.sync.aligned.m16n8k16.row.col.f32.bf16.bf16.f32 "
                 "{%0,%1,%2,%3}, {%4,%5,%6,%7}, {%8,%9}, {%0,%1,%2,%3};"
                 : "+f"(d[0]), "+f"(d[1]), "+f"(d[2]), "+f"(d[3])
                 : "r"(a[0]), "r"(a[1]), "r"(a[2]), "r"(a[3]), "r"(b0), "r"(b1));
}
__device__ __forceinline__ uint32_t pack_bf2(__nv_bfloat16 a, __nv_bfloat16 b) {
    return (uint32_t)__bfloat16_as_ushort(a) | ((uint32_t)__bfloat16_as_ushort(b) << 16);
}

// smem layout (bytes). x tiles: 64 rows x 136 bf16 (pitch 272B)
#define XH_OFF  0
#define XL_OFF  17408
#define OUT_OFF 34816                 // 64 x 132 f32
#define QKV_SMEM (34816 + 64 * 132 * 4)   // 68608

// ---------------- P = softmax(S, axis=1), S: [4][64] ----------------------
__global__ void softmaxS_kernel(const float* __restrict__ S) {
    int t = threadIdx.x;
    int a = t >> 6, c = t & 63;
    float v = __expf(S[a * 64 + c]);
    float s = v;
    #pragma unroll
    for (int o = 16; o; o >>= 1) s += __shfl_xor_sync(0xffffffffu, s, o);
    __shared__ float part[8];
    if ((t & 31) == 0) part[t >> 5] = s;
    __syncthreads();
    float sum = part[a * 2] + part[a * 2 + 1];
    g_P[a * 64 + c] = v / sum;
}

// ---------------- W[k][n] -> packed mma b-frags (bf16 hi/lo) --------------
__global__ void wconv_kernel(const float* __restrict__ Wq,
                             const float* __restrict__ Wk,
                             const float* __restrict__ Wv) {
    int i = blockIdx.x * blockDim.x + threadIdx.x;
    if (i >= 3 * 16384) return;
    int ph = i >> 14, rem = i & 16383;
    int k = rem >> 7, n = rem & 127;                 // coalesced read in n
    const float* W = (ph == 0) ? Wq : (ph == 1) ? Wk : Wv;
    float v = W[k * 128 + n];
    __nv_bfloat16 hi = __float2bfloat16_rn(v);
    __nv_bfloat16 lo = __float2bfloat16_rn(v - __bfloat162float(hi));
    int kt = k >> 4, nt = n >> 3;
    int t  = ((n & 7) << 2) | ((k & 7) >> 1);
    int word = (k >> 3) & 1, half = k & 1;
    size_t base = ((size_t)((ph * 8 + kt) * 16 + nt) * 32 + t) * 8;
    g_Wf[base + word * 2 + half]     = hi;
    g_Wf[base + 4 + word * 2 + half] = lo;
}

// ---------------- fused QKV GEMM (mma.sync bf16 split) + bias + RoPE ------
__global__ __launch_bounds__(256, 2) void qkv_mma_kernel(
    const float* __restrict__ x, const float* __restrict__ ang,
    const float* __restrict__ bq, const float* __restrict__ bk,
    const float* __restrict__ bv, int N)
{
    extern __shared__ char smem[];
    uint32_t sb = smem_u32(smem);
    int tid = threadIdx.x, wid = tid >> 5, lane = tid & 31;
    int row0 = blockIdx.x * 64;

    #pragma unroll
    for (int j = 0; j < 8; ++j) {
        int idx  = tid + 256 * j;
        int row  = idx >> 5;
        int col0 = (idx & 31) * 4;
        int gr   = row0 + row;
        float4 v = make_float4(0.f, 0.f, 0.f, 0.f);
        if (gr < N) v = *reinterpret_cast<const float4*>(&x[(size_t)gr * 128 + col0]);
        __nv_bfloat16 h0 = __float2bfloat16_rn(v.x), h1 = __float2bfloat16_rn(v.y);
        __nv_bfloat16 h2 = __float2bfloat16_rn(v.z), h3 = __float2bfloat16_rn(v.w);
        __nv_bfloat16 l0 = __float2bfloat16_rn(v.x - __bfloat162float(h0));
        __nv_bfloat16 l1 = __float2bfloat16_rn(v.y - __bfloat162float(h1));
        __nv_bfloat16 l2 = __float2bfloat16_rn(v.z - __bfloat162float(h2));
        __nv_bfloat16 l3 = __float2bfloat16_rn(v.w - __bfloat162float(h3));
        uint32_t off = (uint32_t)row * 272u + (uint32_t)col0 * 2u;
        *reinterpret_cast<uint2*>(smem + XH_OFF + off) = make_uint2(pack_bf2(h0, h1), pack_bf2(h2, h3));
        *reinterpret_cast<uint2*>(smem + XL_OFF + off) = make_uint2(pack_bf2(l0, l1), pack_bf2(l2, l3));
    }
    __syncthreads();

    int wm = wid & 3;
    int wn = wid >> 2;
    float* outs = reinterpret_cast<float*>(smem + OUT_OFF);

    for (int ph = 0; ph < 3; ++ph) {
        float d[8][4];
        #pragma unroll
        for (int nj = 0; nj < 8; ++nj)
            #pragma unroll
            for (int q = 0; q < 4; ++q) d[nj][q] = 0.f;

        const uint4* wf = reinterpret_cast<const uint4*>(g_Wf) + ((size_t)ph * 8 * 16 + wn * 8) * 32 + lane;

        #pragma unroll 2
        for (int kk = 0; kk < 8; ++kk) {
            uint32_t ah[4], al[4];
            {
                int r = wm * 16 + (lane & 15);
                int c = kk * 16 + (lane >> 4) * 8;
                uint32_t a = sb + XH_OFF + (uint32_t)r * 272u + (uint32_t)c * 2u;
                ldm_x4(ah, a);
                ldm_x4(al, a + (XL_OFF - XH_OFF));
            }
            uint4 bfr[8];
            #pragma unroll
            for (int nj = 0; nj < 8; ++nj)
                bfr[nj] = wf[((size_t)kk * 16 + nj) * 32];
            #pragma unroll
            for (int nj = 0; nj < 8; ++nj) {
                mma16816(d[nj], ah, bfr[nj].x, bfr[nj].y);
                mma16816(d[nj], ah, bfr[nj].z, bfr[nj].w);
                mma16816(d[nj], al, bfr[nj].x, bfr[nj].y);
            }
        }

        #pragma unroll
        for (int nj = 0; nj < 8; ++nj) {
            int r = wm * 16 + (lane >> 2);
            int c = wn * 64 + nj * 8 + 2 * (lane & 3);
            *reinterpret_cast<float2*>(&outs[r * 132 + c])       = make_float2(d[nj][0], d[nj][1]);
            *reinterpret_cast<float2*>(&outs[(r + 8) * 132 + c]) = make_float2(d[nj][2], d[nj][3]);
        }
        __syncthreads();

        {
            const float* bias = (ph == 0) ? bq : (ph == 1) ? bk : bv;
            #pragma unroll
            for (int rr = 0; rr < 8; ++rr) {
                int row = wid * 8 + rr;
                int n = row0 + row;
                if (n >= N) break;
                int j0 = lane * 4;
                const float* orow = &outs[row * 132];
                float v0 = orow[j0 + 0] + bias[j0 + 0];
                float v1 = orow[j0 + 1] + bias[j0 + 1];
                float v2 = orow[j0 + 2] + bias[j0 + 2];
                float v3 = orow[j0 + 3] + bias[j0 + 3];
                float4 ov;
                if (ph < 2) {
                    float a0 = ang[n * 4 + 0], a1 = ang[n * 4 + 1];
                    float a2 = ang[n * 4 + 2], a3 = ang[n * 4 + 3];
                    int m0 = 2 * lane, m1 = 2 * lane + 1;
                    float t0 = a0 * g_P[m0] + a1 * g_P[64 + m0] + a2 * g_P[128 + m0] + a3 * g_P[192 + m0];
                    float t1 = a0 * g_P[m1] + a1 * g_P[64 + m1] + a2 * g_P[128 + m1] + a3 * g_P[192 + m1];
                    float c0, s0, c1, s1;
                    __sincosf(t0, &s0, &c0);
                    __sincosf(t1, &s1, &c1);
                    float pv[4];
                    #pragma unroll
                    for (int i = 0; i < 4; ++i) {
                        int j = j0 + i;
                        int jj = j & 15, hb = j & 0x70;
                        int p; float sg;
                        if (jj < 8) { p = hb + 2 * jj + 1;  sg = -1.f; }
                        else        { p = hb + 2 * jj - 16; sg =  1.f; }
                        pv[i] = sg * (orow[p] + bias[p]);
                    }
                    ov.x = v0 * c0 + pv[0] * s0;
                    ov.y = v1 * c0 + pv[1] * s0;
                    ov.z = v2 * c1 + pv[2] * s1;
                    ov.w = v3 * c1 + pv[3] * s1;
                } else {
                    ov = make_float4(v0, v1, v2, v3);
                }
                if (ph == 0) {
                    *reinterpret_cast<float4*>(&g_Q[(size_t)n * 128 + j0]) = ov;
                } else {
                    __half2 h01 = __floats2half2_rn(ov.x, ov.y);
                    __half2 h23 = __floats2half2_rn(ov.z, ov.w);
                    uint2 pk = make_uint2(*reinterpret_cast<uint32_t*>(&h01),
                                          *reinterpret_cast<uint32_t*>(&h23));
                    size_t gi = (size_t)n * 256 + (ph == 1 ? 0 : 128) + j0;
                    *reinterpret_cast<uint2*>(&g_KVh[gi]) = pk;
                }
            }
        }
        __syncthreads();
    }
}

// ---------------- CSR build: zero counts, histogram, scan, scatter --------
__global__ void zero_cnt_kernel(int N) {
    int i = blockIdx.x * blockDim.x + threadIdx.x;
    if (i <= N) g_cnt[i] = 0;
}
__global__ void hist_kernel(const int* __restrict__ ei, int E) {
    int e = blockIdx.x * blockDim.x + threadIdx.x;
    if (e < E) atomicAdd(&g_cnt[ei[E + e]], 1);
}
__global__ __launch_bounds__(1024) void scan_kernel(int N) {
    __shared__ int sums[1024];
    int t = threadIdx.x;
    int chunk = (N + 1023) / 1024;
    int lo = t * chunk, hi = min(lo + chunk, N);
    int s = 0;
    for (int i = lo; i < hi; ++i) s += g_cnt[i];
    sums[t] = s;
    __syncthreads();
    #pragma unroll
    for (int off = 1; off < 1024; off <<= 1) {
        int v = (t >= off) ? sums[t - off] : 0;
        __syncthreads();
        sums[t] += v;
        __syncthreads();
    }
    int base = sums[t] - s;
    for (int i = lo; i < hi; ++i) {
        g_off[i] = base;
        g_pos[i] = base;
        base += g_cnt[i];
    }
    if (t == 1023) g_off[N] = sums[1023];
}
__global__ void scatter_kernel(const int* __restrict__ ei, int E) {
    int e = blockIdx.x * blockDim.x + threadIdx.x;
    if (e >= E) return;
    int src = ei[e];
    int dst = ei[E + e];
    int p = atomicAdd(&g_pos[dst], 1);
    g_esrc[p] = src;
}

// ---------------- aggregation: warp per dst, double-buffered prefetch -----
#define AGG_FETCH(I, S0,S1,S2,S3, K0,K1,K2,K3, V0,V1,V2,V3)                    \
    do {                                                                       \
        S0 = g_esrc[(I)];                                                      \
        S1 = ((I) + 1 < end) ? g_esrc[(I) + 1] : -1;                           \
        S2 = ((I) + 2 < end) ? g_esrc[(I) + 2] : -1;                           \
        S3 = ((I) + 3 < end) ? g_esrc[(I) + 3] : -1;                           \
        int A0 = S0, A1 = (S1 < 0) ? 0 : S1;                                   \
        int A2 = (S2 < 0) ? 0 : S2, A3 = (S3 < 0) ? 0 : S3;                    \
        K0 = kv[A0 * 64 + lane];        K1 = kv[A1 * 64 + lane];               \
        K2 = kv[A2 * 64 + lane];        K3 = kv[A3 * 64 + lane];               \
        V0 = kv[A0 * 64 + 32 + lane];   V1 = kv[A1 * 64 + 32 + lane];          \
        V2 = kv[A2 * 64 + 32 + lane];   V3 = kv[A3 * 64 + 32 + lane];          \
    } while (0)

__global__ __launch_bounds__(256) void agg_kernel(float* __restrict__ out, int N) {
    int w    = (blockIdx.x * blockDim.x + threadIdx.x) >> 5;
    int lane = threadIdx.x & 31;
    if (w >= N) return;
    int beg = g_off[w], end = g_off[w + 1];

    float4 q4 = reinterpret_cast<const float4*>(g_Q)[w * 32 + lane];
    float4 acc = make_float4(0.f, 0.f, 0.f, 0.f);
    float ssum = 0.f;
    const uint2* kv = reinterpret_cast<const uint2*>(g_KVh);

    if (beg < end) {
        // current batch registers
        int cs0, cs1, cs2, cs3;
        uint2 cK0, cK1, cK2, cK3, cV0, cV1, cV2, cV3;
        AGG_FETCH(beg, cs0, cs1, cs2, cs3, cK0, cK1, cK2, cK3, cV0, cV1, cV2, cV3);

        for (int i = beg; i < end; i += 4) {
            int nx = i + 4;
            bool hasNext = nx < end;
            // prefetch next batch BEFORE computing current one
            int ns0 = 0, ns1 = -1, ns2 = -1, ns3 = -1;
            uint2 nK0, nK1, nK2, nK3, nV0, nV1, nV2, nV3;
            if (hasNext)
                AGG_FETCH(nx, ns0, ns1, ns2, ns3, nK0, nK1, nK2, nK3, nV0, nV1, nV2, nV3);

            // ---- compute current batch ----
            float2 k0a = __half22float2(*reinterpret_cast<__half2*>(&cK0.x));
            float2 k0b = __half22float2(*reinterpret_cast<__half2*>(&cK0.y));
            float2 k1a = __half22float2(*reinterpret_cast<__half2*>(&cK1.x));
            float2 k1b = __half22float2(*reinterpret_cast<__half2*>(&cK1.y));
            float2 k2a = __half22float2(*reinterpret_cast<__half2*>(&cK2.x));
            float2 k2b = __half22float2(*reinterpret_cast<__half2*>(&cK2.y));
            float2 k3a = __half22float2(*reinterpret_cast<__half2*>(&cK3.x));
            float2 k3b = __half22float2(*reinterpret_cast<__half2*>(&cK3.y));

            float p0 = k0a.x * q4.x + k0a.y * q4.y + k0b.x * q4.z + k0b.y * q4.w;
            float p1 = k1a.x * q4.x + k1a.y * q4.y + k1b.x * q4.z + k1b.y * q4.w;
            float p2 = k2a.x * q4.x + k2a.y * q4.y + k2b.x * q4.z + k2b.y * q4.w;
            float p3 = k3a.x * q4.x + k3a.y * q4.y + k3b.x * q4.z + k3b.y * q4.w;
            p0 += __shfl_xor_sync(0xffffffffu, p0, 1);
            p1 += __shfl_xor_sync(0xffffffffu, p1, 1);
            p2 += __shfl_xor_sync(0xffffffffu, p2, 1);
            p3 += __shfl_xor_sync(0xffffffffu, p3, 1);
            p0 += __shfl_xor_sync(0xffffffffu, p0, 2);
            p1 += __shfl_xor_sync(0xffffffffu, p1, 2);
            p2 += __shfl_xor_sync(0xffffffffu, p2, 2);
            p3 += __shfl_xor_sync(0xffffffffu, p3, 2);

            float w0 = __expf(fminf(fmaxf(p0 * 0.25f, -5.f), 5.f));
            float w1 = (cs1 < 0) ? 0.f : __expf(fminf(fmaxf(p1 * 0.25f, -5.f), 5.f));
            float w2 = (cs2 < 0) ? 0.f : __expf(fminf(fmaxf(p2 * 0.25f, -5.f), 5.f));
            float w3 = (cs3 < 0) ? 0.f : __expf(fminf(fmaxf(p3 * 0.25f, -5.f), 5.f));

            float2 v0a = __half22float2(*reinterpret_cast<__half2*>(&cV0.x));
            float2 v0b = __half22float2(*reinterpret_cast<__half2*>(&cV0.y));
            float2 v1a = __half22float2(*reinterpret_cast<__half2*>(&cV1.x));
            float2 v1b = __half22float2(*reinterpret_cast<__half2*>(&cV1.y));
            float2 v2a = __half22float2(*reinterpret_cast<__half2*>(&cV2.x));
            float2 v2b = __half22float2(*reinterpret_cast<__half2*>(&cV2.y));
            float2 v3a = __half22float2(*reinterpret_cast<__half2*>(&cV3.x));
            float2 v3b = __half22float2(*reinterpret_cast<__half2*>(&cV3.y));

            ssum += (w0 + w1) + (w2 + w3);
            acc.x += w0 * v0a.x + w1 * v1a.x + w2 * v2a.x + w3 * v3a.x;
            acc.y += w0 * v0a.y + w1 * v1a.y + w2 * v2a.y + w3 * v3a.y;
            acc.z += w0 * v0b.x + w1 * v1b.x + w2 * v2b.x + w3 * v3b.x;
            acc.w += w0 * v0b.y + w1 * v1b.y + w2 * v2b.y + w3 * v3b.y;

            // ---- rotate prefetched batch into current ----
            if (hasNext) {
                cs0 = ns0; cs1 = ns1; cs2 = ns2; cs3 = ns3;
                cK0 = nK0; cK1 = nK1; cK2 = nK2; cK3 = nK3;
                cV0 = nV0; cV1 = nV1; cV2 = nV2; cV3 = nV3;
            }
        }
    }
    float inv = 1.f / (ssum + 1e-16f);
    reinterpret_cast<float4*>(out)[w * 32 + lane] =
        make_float4(acc.x * inv, acc.y * inv, acc.z * inv, acc.w * inv);
}

// ---------------- launch: two-stream overlap (CSR prep || QKV GEMM) -------
extern "C" void kernel_launch(void* const* d_in, const int* in_sizes, int n_in,
                              void* d_out, int out_size)
{
    const float* x   = (const float*)d_in[0];
    const float* ang = (const float*)d_in[1];
    const int*   ei  = (const int*)  d_in[2];
    const float* Wq  = (const float*)d_in[3];
    const float* bq  = (const float*)d_in[4];
    const float* Wk  = (const float*)d_in[5];
    const float* bk  = (const float*)d_in[6];
    const float* Wv  = (const float*)d_in[7];
    const float* bv  = (const float*)d_in[8];
    const float* S   = (const float*)d_in[9];
    float* out = (float*)d_out;

    int N = in_sizes[0] / 128;
    int E = in_sizes[2] / 2;

    static cudaStream_t s2 = nullptr;
    static cudaEvent_t evFork = nullptr, evJoin = nullptr;
    static bool attr_done = false;
    if (!attr_done) {
        cudaFuncSetAttribute(qkv_mma_kernel,
                             cudaFuncAttributeMaxDynamicSharedMemorySize, QKV_SMEM);
        cudaStreamCreateWithFlags(&s2, cudaStreamNonBlocking);
        cudaEventCreateWithFlags(&evFork, cudaEventDisableTiming);
        cudaEventCreateWithFlags(&evJoin, cudaEventDisableTiming);
        attr_done = true;
    }

    cudaEventRecord(evFork, 0);
    cudaStreamWaitEvent(s2, evFork, 0);

    // side stream: CSR build
    zero_cnt_kernel<<<(N + 256) / 256, 256, 0, s2>>>(N);
    hist_kernel<<<(E + 255) / 256, 256, 0, s2>>>(ei, E);
    scan_kernel<<<1, 1024, 0, s2>>>(N);
    scatter_kernel<<<(E + 255) / 256, 256, 0, s2>>>(ei, E);
    cudaEventRecord(evJoin, s2);

    // main stream: projection path
    softmaxS_kernel<<<1, 256>>>(S);
    wconv_kernel<<<(3 * 16384 + 255) / 256, 256>>>(Wq, Wk, Wv);
    qkv_mma_kernel<<<(N + 63) / 64, 256, QKV_SMEM>>>(x, ang, bq, bk, bv, N);

    cudaStreamWaitEvent(0, evJoin, 0);
    agg_kernel<<<(N + 7) / 8, 256>>>(out, N);
}

// round 12
// speedup vs baseline: 1.0525x; 1.0525x over previous
#include <cuda_runtime.h>
#include <cuda_bf16.h>
#include <cuda_fp16.h>
#include <cstdint>

#define N_NODES 50000
#define MAX_E   800000

// ---------------- device scratch ------------------------------------------
__device__ float g_Q[N_NODES * 128];
__device__ __half g_KVh[N_NODES * 256];            // [node][K:128 | V:128] fp16
__device__ float g_P[256];                         // softmax(S): [4][64]
// W packed in mma b-frag order: [ph][kt:8][nt:16][lane:32][8 bf16: hi w0b0,w0b1,w1b0,w1b1, lo ...]
__device__ __nv_bfloat16 g_Wf[3 * 8 * 16 * 32 * 8];
// CSR scratch
__device__ int g_cnt[N_NODES + 1];
__device__ int g_off[N_NODES + 1];
__device__ int g_pos[N_NODES + 1];
__device__ int g_esrc[MAX_E];

// ---------------- helpers --------------------------------------------------
__device__ __forceinline__ uint32_t smem_u32(const void* p) {
    uint32_t a;
    asm("{ .reg .u64 t; cvta.to.shared.u64 t, %1; cvt.u32.u64 %0, t; }" : "=r"(a) : "l"(p));
    return a;
}
__device__ __forceinline__ void ldm_x4(uint32_t* r, uint32_t addr) {
    asm volatile("ldmatrix.sync.aligned.m8n8.x4.shared.b16 {%0,%1,%2,%3}, [%4];"
                 : "=r"(r[0]), "=r"(r[1]), "=r"(r[2]), "=r"(r[3]) : "r"(addr));
}
__device__ __forceinline__ void mma16816(float* d, const uint32_t* a, uint32_t b0, uint32_t b1) {
    asm volatile("mma.sync.aligned.m16n8k16.row.col.f32.bf16.bf16.f32 "
                 "{%0,%1,%2,%3}, {%4,%5,%6,%7}, {%8,%9}, {%0,%1,%2,%3};"
                 : "+f"(d[0]), "+f"(d[1]), "+f"(d[2]), "+f"(d[3])
                 : "r"(a[0]), "r"(a[1]), "r"(a[2]), "r"(a[3]), "r"(b0), "r"(b1));
}
__device__ __forceinline__ uint32_t pack_bf2(__nv_bfloat16 a, __nv_bfloat16 b) {
    return (uint32_t)__bfloat16_as_ushort(a) | ((uint32_t)__bfloat16_as_ushort(b) << 16);
}

// smem layout (bytes). x tiles: 64 rows x 136 bf16 (pitch 272B)
#define XH_OFF  0
#define XL_OFF  17408
#define OUT_OFF 34816                 // 64 x 132 f32
#define QKV_SMEM (34816 + 64 * 132 * 4)   // 68608

// ---------------- P = softmax(S, axis=1), S: [4][64] ----------------------
__global__ void softmaxS_kernel(const float* __restrict__ S) {
    int t = threadIdx.x;
    int a = t >> 6, c = t & 63;
    float v = __expf(S[a * 64 + c]);
    float s = v;
    #pragma unroll
    for (int o = 16; o; o >>= 1) s += __shfl_xor_sync(0xffffffffu, s, o);
    __shared__ float part[8];
    if ((t & 31) == 0) part[t >> 5] = s;
    __syncthreads();
    float sum = part[a * 2] + part[a * 2 + 1];
    g_P[a * 64 + c] = v / sum;
}

// ---------------- W[k][n] -> packed mma b-frags (bf16 hi/lo) --------------
__global__ void wconv_kernel(const float* __restrict__ Wq,
                             const float* __restrict__ Wk,
                             const float* __restrict__ Wv) {
    int i = blockIdx.x * blockDim.x + threadIdx.x;
    if (i >= 3 * 16384) return;
    int ph = i >> 14, rem = i & 16383;
    int k = rem >> 7, n = rem & 127;                 // coalesced read in n
    const float* W = (ph == 0) ? Wq : (ph == 1) ? Wk : Wv;
    float v = W[k * 128 + n];
    __nv_bfloat16 hi = __float2bfloat16_rn(v);
    __nv_bfloat16 lo = __float2bfloat16_rn(v - __bfloat162float(hi));
    int kt = k >> 4, nt = n >> 3;
    int t  = ((n & 7) << 2) | ((k & 7) >> 1);
    int word = (k >> 3) & 1, half = k & 1;
    size_t base = ((size_t)((ph * 8 + kt) * 16 + nt) * 32 + t) * 8;
    g_Wf[base + word * 2 + half]     = hi;
    g_Wf[base + 4 + word * 2 + half] = lo;
}

// ---------------- fused QKV GEMM (mma.sync bf16 split) + bias + RoPE ------
__global__ __launch_bounds__(256, 2) void qkv_mma_kernel(
    const float* __restrict__ x, const float* __restrict__ ang,
    const float* __restrict__ bq, const float* __restrict__ bk,
    const float* __restrict__ bv, int N)
{
    extern __shared__ char smem[];
    uint32_t sb = smem_u32(smem);
    int tid = threadIdx.x, wid = tid >> 5, lane = tid & 31;
    int row0 = blockIdx.x * 64;

    #pragma unroll
    for (int j = 0; j < 8; ++j) {
        int idx  = tid + 256 * j;
        int row  = idx >> 5;
        int col0 = (idx & 31) * 4;
        int gr   = row0 + row;
        float4 v = make_float4(0.f, 0.f, 0.f, 0.f);
        if (gr < N) v = *reinterpret_cast<const float4*>(&x[(size_t)gr * 128 + col0]);
        __nv_bfloat16 h0 = __float2bfloat16_rn(v.x), h1 = __float2bfloat16_rn(v.y);
        __nv_bfloat16 h2 = __float2bfloat16_rn(v.z), h3 = __float2bfloat16_rn(v.w);
        __nv_bfloat16 l0 = __float2bfloat16_rn(v.x - __bfloat162float(h0));
        __nv_bfloat16 l1 = __float2bfloat16_rn(v.y - __bfloat162float(h1));
        __nv_bfloat16 l2 = __float2bfloat16_rn(v.z - __bfloat162float(h2));
        __nv_bfloat16 l3 = __float2bfloat16_rn(v.w - __bfloat162float(h3));
        uint32_t off = (uint32_t)row * 272u + (uint32_t)col0 * 2u;
        *reinterpret_cast<uint2*>(smem + XH_OFF + off) = make_uint2(pack_bf2(h0, h1), pack_bf2(h2, h3));
        *reinterpret_cast<uint2*>(smem + XL_OFF + off) = make_uint2(pack_bf2(l0, l1), pack_bf2(l2, l3));
    }
    __syncthreads();

    int wm = wid & 3;
    int wn = wid >> 2;
    float* outs = reinterpret_cast<float*>(smem + OUT_OFF);

    for (int ph = 0; ph < 3; ++ph) {
        float d[8][4];
        #pragma unroll
        for (int nj = 0; nj < 8; ++nj)
            #pragma unroll
            for (int q = 0; q < 4; ++q) d[nj][q] = 0.f;

        const uint4* wf = reinterpret_cast<const uint4*>(g_Wf) + ((size_t)ph * 8 * 16 + wn * 8) * 32 + lane;

        #pragma unroll 2
        for (int kk = 0; kk < 8; ++kk) {
            uint32_t ah[4], al[4];
            {
                int r = wm * 16 + (lane & 15);
                int c = kk * 16 + (lane >> 4) * 8;
                uint32_t a = sb + XH_OFF + (uint32_t)r * 272u + (uint32_t)c * 2u;
                ldm_x4(ah, a);
                ldm_x4(al, a + (XL_OFF - XH_OFF));
            }
            uint4 bfr[8];
            #pragma unroll
            for (int nj = 0; nj < 8; ++nj)
                bfr[nj] = wf[((size_t)kk * 16 + nj) * 32];
            #pragma unroll
            for (int nj = 0; nj < 8; ++nj) {
                mma16816(d[nj], ah, bfr[nj].x, bfr[nj].y);
                mma16816(d[nj], ah, bfr[nj].z, bfr[nj].w);
                mma16816(d[nj], al, bfr[nj].x, bfr[nj].y);
            }
        }

        #pragma unroll
        for (int nj = 0; nj < 8; ++nj) {
            int r = wm * 16 + (lane >> 2);
            int c = wn * 64 + nj * 8 + 2 * (lane & 3);
            *reinterpret_cast<float2*>(&outs[r * 132 + c])       = make_float2(d[nj][0], d[nj][1]);
            *reinterpret_cast<float2*>(&outs[(r + 8) * 132 + c]) = make_float2(d[nj][2], d[nj][3]);
        }
        __syncthreads();

        {
            const float* bias = (ph == 0) ? bq : (ph == 1) ? bk : bv;
            #pragma unroll
            for (int rr = 0; rr < 8; ++rr) {
                int row = wid * 8 + rr;
                int n = row0 + row;
                if (n >= N) break;
                int j0 = lane * 4;
                const float* orow = &outs[row * 132];
                float v0 = orow[j0 + 0] + bias[j0 + 0];
                float v1 = orow[j0 + 1] + bias[j0 + 1];
                float v2 = orow[j0 + 2] + bias[j0 + 2];
                float v3 = orow[j0 + 3] + bias[j0 + 3];
                float4 ov;
                if (ph < 2) {
                    float a0 = ang[n * 4 + 0], a1 = ang[n * 4 + 1];
                    float a2 = ang[n * 4 + 2], a3 = ang[n * 4 + 3];
                    int m0 = 2 * lane, m1 = 2 * lane + 1;
                    float t0 = a0 * g_P[m0] + a1 * g_P[64 + m0] + a2 * g_P[128 + m0] + a3 * g_P[192 + m0];
                    float t1 = a0 * g_P[m1] + a1 * g_P[64 + m1] + a2 * g_P[128 + m1] + a3 * g_P[192 + m1];
                    float c0, s0, c1, s1;
                    __sincosf(t0, &s0, &c0);
                    __sincosf(t1, &s1, &c1);
                    float pv[4];
                    #pragma unroll
                    for (int i = 0; i < 4; ++i) {
                        int j = j0 + i;
                        int jj = j & 15, hb = j & 0x70;
                        int p; float sg;
                        if (jj < 8) { p = hb + 2 * jj + 1;  sg = -1.f; }
                        else        { p = hb + 2 * jj - 16; sg =  1.f; }
                        pv[i] = sg * (orow[p] + bias[p]);
                    }
                    ov.x = v0 * c0 + pv[0] * s0;
                    ov.y = v1 * c0 + pv[1] * s0;
                    ov.z = v2 * c1 + pv[2] * s1;
                    ov.w = v3 * c1 + pv[3] * s1;
                } else {
                    ov = make_float4(v0, v1, v2, v3);
                }
                if (ph == 0) {
                    *reinterpret_cast<float4*>(&g_Q[(size_t)n * 128 + j0]) = ov;
                } else {
                    __half2 h01 = __floats2half2_rn(ov.x, ov.y);
                    __half2 h23 = __floats2half2_rn(ov.z, ov.w);
                    uint2 pk = make_uint2(*reinterpret_cast<uint32_t*>(&h01),
                                          *reinterpret_cast<uint32_t*>(&h23));
                    size_t gi = (size_t)n * 256 + (ph == 1 ? 0 : 128) + j0;
                    *reinterpret_cast<uint2*>(&g_KVh[gi]) = pk;
                }
            }
        }
        __syncthreads();
    }
}

// ---------------- CSR build: zero counts, histogram, scan, scatter --------
__global__ void zero_cnt_kernel(int N) {
    int i = blockIdx.x * blockDim.x + threadIdx.x;
    if (i <= N) g_cnt[i] = 0;
}
__global__ void hist_kernel(const int* __restrict__ ei, int E) {
    int e = blockIdx.x * blockDim.x + threadIdx.x;
    if (e < E) atomicAdd(&g_cnt[ei[E + e]], 1);
}
__global__ __launch_bounds__(1024) void scan_kernel(int N) {
    __shared__ int sums[1024];
    int t = threadIdx.x;
    int chunk = (N + 1023) / 1024;
    int lo = t * chunk, hi = min(lo + chunk, N);
    int s = 0;
    for (int i = lo; i < hi; ++i) s += g_cnt[i];
    sums[t] = s;
    __syncthreads();
    #pragma unroll
    for (int off = 1; off < 1024; off <<= 1) {
        int v = (t >= off) ? sums[t - off] : 0;
        __syncthreads();
        sums[t] += v;
        __syncthreads();
    }
    int base = sums[t] - s;
    for (int i = lo; i < hi; ++i) {
        g_off[i] = base;
        g_pos[i] = base;
        base += g_cnt[i];
    }
    if (t == 1023) g_off[N] = sums[1023];
}
__global__ void scatter_kernel(const int* __restrict__ ei, int E) {
    int e = blockIdx.x * blockDim.x + threadIdx.x;
    if (e >= E) return;
    int src = ei[e];
    int dst = ei[E + e];
    int p = atomicAdd(&g_pos[dst], 1);
    g_esrc[p] = src;
}

// ---------------- aggregation: 2 warps/block (HW-scheduled balance) -------
__global__ __launch_bounds__(64) void agg_kernel(float* __restrict__ out, int N) {
    int w    = (blockIdx.x * blockDim.x + threadIdx.x) >> 5;
    int lane = threadIdx.x & 31;
    if (w >= N) return;
    int beg = g_off[w], end = g_off[w + 1];

    float4 q4 = reinterpret_cast<const float4*>(g_Q)[w * 32 + lane];
    float4 acc = make_float4(0.f, 0.f, 0.f, 0.f);
    float ssum = 0.f;
    const uint2* kv = reinterpret_cast<const uint2*>(g_KVh);

    for (int i = beg; i < end; i += 4) {
        int s0 = g_esrc[i];
        int s1 = (i + 1 < end) ? g_esrc[i + 1] : -1;
        int s2 = (i + 2 < end) ? g_esrc[i + 2] : -1;
        int s3 = (i + 3 < end) ? g_esrc[i + 3] : -1;
        int a0 = s0, a1 = (s1 < 0) ? 0 : s1, a2 = (s2 < 0) ? 0 : s2, a3 = (s3 < 0) ? 0 : s3;
        uint2 K0 = kv[a0 * 64 + lane];
        uint2 K1 = kv[a1 * 64 + lane];
        uint2 K2 = kv[a2 * 64 + lane];
        uint2 K3 = kv[a3 * 64 + lane];
        uint2 V0 = kv[a0 * 64 + 32 + lane];
        uint2 V1 = kv[a1 * 64 + 32 + lane];
        uint2 V2 = kv[a2 * 64 + 32 + lane];
        uint2 V3 = kv[a3 * 64 + 32 + lane];

        float2 k0a = __half22float2(*reinterpret_cast<__half2*>(&K0.x));
        float2 k0b = __half22float2(*reinterpret_cast<__half2*>(&K0.y));
        float2 k1a = __half22float2(*reinterpret_cast<__half2*>(&K1.x));
        float2 k1b = __half22float2(*reinterpret_cast<__half2*>(&K1.y));
        float2 k2a = __half22float2(*reinterpret_cast<__half2*>(&K2.x));
        float2 k2b = __half22float2(*reinterpret_cast<__half2*>(&K2.y));
        float2 k3a = __half22float2(*reinterpret_cast<__half2*>(&K3.x));
        float2 k3b = __half22float2(*reinterpret_cast<__half2*>(&K3.y));

        float p0 = k0a.x * q4.x + k0a.y * q4.y + k0b.x * q4.z + k0b.y * q4.w;
        float p1 = k1a.x * q4.x + k1a.y * q4.y + k1b.x * q4.z + k1b.y * q4.w;
        float p2 = k2a.x * q4.x + k2a.y * q4.y + k2b.x * q4.z + k2b.y * q4.w;
        float p3 = k3a.x * q4.x + k3a.y * q4.y + k3b.x * q4.z + k3b.y * q4.w;
        p0 += __shfl_xor_sync(0xffffffffu, p0, 1);
        p1 += __shfl_xor_sync(0xffffffffu, p1, 1);
        p2 += __shfl_xor_sync(0xffffffffu, p2, 1);
        p3 += __shfl_xor_sync(0xffffffffu, p3, 1);
        p0 += __shfl_xor_sync(0xffffffffu, p0, 2);
        p1 += __shfl_xor_sync(0xffffffffu, p1, 2);
        p2 += __shfl_xor_sync(0xffffffffu, p2, 2);
        p3 += __shfl_xor_sync(0xffffffffu, p3, 2);

        float w0 = __expf(fminf(fmaxf(p0 * 0.25f, -5.f), 5.f));
        float w1 = (s1 < 0) ? 0.f : __expf(fminf(fmaxf(p1 * 0.25f, -5.f), 5.f));
        float w2 = (s2 < 0) ? 0.f : __expf(fminf(fmaxf(p2 * 0.25f, -5.f), 5.f));
        float w3 = (s3 < 0) ? 0.f : __expf(fminf(fmaxf(p3 * 0.25f, -5.f), 5.f));

        float2 v0a = __half22float2(*reinterpret_cast<__half2*>(&V0.x));
        float2 v0b = __half22float2(*reinterpret_cast<__half2*>(&V0.y));
        float2 v1a = __half22float2(*reinterpret_cast<__half2*>(&V1.x));
        float2 v1b = __half22float2(*reinterpret_cast<__half2*>(&V1.y));
        float2 v2a = __half22float2(*reinterpret_cast<__half2*>(&V2.x));
        float2 v2b = __half22float2(*reinterpret_cast<__half2*>(&V2.y));
        float2 v3a = __half22float2(*reinterpret_cast<__half2*>(&V3.x));
        float2 v3b = __half22float2(*reinterpret_cast<__half2*>(&V3.y));

        ssum += (w0 + w1) + (w2 + w3);
        acc.x += w0 * v0a.x + w1 * v1a.x + w2 * v2a.x + w3 * v3a.x;
        acc.y += w0 * v0a.y + w1 * v1a.y + w2 * v2a.y + w3 * v3a.y;
        acc.z += w0 * v0b.x + w1 * v1b.x + w2 * v2b.x + w3 * v3b.x;
        acc.w += w0 * v0b.y + w1 * v1b.y + w2 * v2b.y + w3 * v3b.y;
    }
    float inv = 1.f / (ssum + 1e-16f);
    reinterpret_cast<float4*>(out)[w * 32 + lane] =
        make_float4(acc.x * inv, acc.y * inv, acc.z * inv, acc.w * inv);
}

// ---------------- launch: two-stream overlap (CSR prep || QKV GEMM) -------
extern "C" void kernel_launch(void* const* d_in, const int* in_sizes, int n_in,
                              void* d_out, int out_size)
{
    const float* x   = (const float*)d_in[0];
    const float* ang = (const float*)d_in[1];
    const int*   ei  = (const int*)  d_in[2];
    const float* Wq  = (const float*)d_in[3];
    const float* bq  = (const float*)d_in[4];
    const float* Wk  = (const float*)d_in[5];
    const float* bk  = (const float*)d_in[6];
    const float* Wv  = (const float*)d_in[7];
    const float* bv  = (const float*)d_in[8];
    const float* S   = (const float*)d_in[9];
    float* out = (float*)d_out;

    int N = in_sizes[0] / 128;
    int E = in_sizes[2] / 2;

    static cudaStream_t s2 = nullptr;
    static cudaEvent_t evFork = nullptr, evJoin = nullptr;
    static bool attr_done = false;
    if (!attr_done) {
        cudaFuncSetAttribute(qkv_mma_kernel,
                             cudaFuncAttributeMaxDynamicSharedMemorySize, QKV_SMEM);
        cudaStreamCreateWithFlags(&s2, cudaStreamNonBlocking);
        cudaEventCreateWithFlags(&evFork, cudaEventDisableTiming);
        cudaEventCreateWithFlags(&evJoin, cudaEventDisableTiming);
        attr_done = true;
    }

    cudaEventRecord(evFork, 0);
    cudaStreamWaitEvent(s2, evFork, 0);

    // side stream: CSR build
    zero_cnt_kernel<<<(N + 256) / 256, 256, 0, s2>>>(N);
    hist_kernel<<<(E + 255) / 256, 256, 0, s2>>>(ei, E);
    scan_kernel<<<1, 1024, 0, s2>>>(N);
    scatter_kernel<<<(E + 255) / 256, 256, 0, s2>>>(ei, E);
    cudaEventRecord(evJoin, s2);

    // main stream: projection path
    softmaxS_kernel<<<1, 256>>>(S);
    wconv_kernel<<<(3 * 16384 + 255) / 256, 256>>>(Wq, Wk, Wv);
    qkv_mma_kernel<<<(N + 63) / 64, 256, QKV_SMEM>>>(x, ang, bq, bk, bv, N);

    cudaStreamWaitEvent(0, evJoin, 0);
    agg_kernel<<<(N + 1) / 2, 64>>>(out, N);
}